// round 2
// baseline (speedup 1.0000x reference)
#include <cuda_runtime.h>
#include <cuda_bf16.h>

// CrossNet collapsed algebraically:
//   xi_l = x0 * a_l + Bsum_l,  a_0 = 1, Bsum_0 = 0
//   s_l  = a_l * d_l + c_l,    d_l = dot(x0, W[l]),  c_l = dot(Bsum_l, W[l])
//   a_{l+1} = a_l + s_l
//   out = x0 * a_3 + (B0 + B1 + B2)
// The three d_l dots are INDEPENDENT -> one fused pass over x0, parallel
// reductions, tiny scalar recurrence, single write. DRAM traffic = 128 MB min.

#define DIMV 256   // float4s per row (DIM=1024)
#define PASSES 8   // 256 / 32 lanes

__global__ __launch_bounds__(256) void crossnet_kernel(
    const float4* __restrict__ x0,
    const float4* __restrict__ W,
    const float4* __restrict__ Bm,
    float4* __restrict__ out,
    int batch)
{
    const int warp_global = (blockIdx.x * blockDim.x + threadIdx.x) >> 5;
    const int lane = threadIdx.x & 31;
    if (warp_global >= batch) return;

    const float4* xrow = x0 + (size_t)warp_global * DIMV;

    float4 x[PASSES];
    float d0 = 0.f, d1 = 0.f, d2 = 0.f;   // dot(x0, W[l])
    float c1 = 0.f, c2 = 0.f;             // dot(B0, W1), dot(B0+B1, W2)

#pragma unroll
    for (int p = 0; p < PASSES; ++p) {
        const int idx = p * 32 + lane;
        x[p] = xrow[idx];                       // DRAM (the only big read)
        float4 w0 = W[idx];                     // L1/L2 resident
        float4 w1 = W[DIMV + idx];
        float4 w2 = W[2 * DIMV + idx];
        float4 b0 = Bm[idx];
        float4 b1 = Bm[DIMV + idx];

        d0 = fmaf(x[p].x, w0.x, d0); d0 = fmaf(x[p].y, w0.y, d0);
        d0 = fmaf(x[p].z, w0.z, d0); d0 = fmaf(x[p].w, w0.w, d0);

        d1 = fmaf(x[p].x, w1.x, d1); d1 = fmaf(x[p].y, w1.y, d1);
        d1 = fmaf(x[p].z, w1.z, d1); d1 = fmaf(x[p].w, w1.w, d1);

        d2 = fmaf(x[p].x, w2.x, d2); d2 = fmaf(x[p].y, w2.y, d2);
        d2 = fmaf(x[p].z, w2.z, d2); d2 = fmaf(x[p].w, w2.w, d2);

        c1 = fmaf(b0.x, w1.x, c1); c1 = fmaf(b0.y, w1.y, c1);
        c1 = fmaf(b0.z, w1.z, c1); c1 = fmaf(b0.w, w1.w, c1);

        c2 = fmaf(b0.x + b1.x, w2.x, c2); c2 = fmaf(b0.y + b1.y, w2.y, c2);
        c2 = fmaf(b0.z + b1.z, w2.z, c2); c2 = fmaf(b0.w + b1.w, w2.w, c2);
    }

    // Five independent warp reductions (pipelined shuffle chains)
#pragma unroll
    for (int o = 16; o > 0; o >>= 1) {
        d0 += __shfl_xor_sync(0xffffffffu, d0, o);
        d1 += __shfl_xor_sync(0xffffffffu, d1, o);
        d2 += __shfl_xor_sync(0xffffffffu, d2, o);
        c1 += __shfl_xor_sync(0xffffffffu, c1, o);
        c2 += __shfl_xor_sync(0xffffffffu, c2, o);
    }

    // Scalar recurrence: a_{l+1} = a_l + (a_l * d_l + c_l),  c_0 = 0
    float a = 1.0f;
    float s = a * d0;            a += s;
    s = fmaf(a, d1, c1);         a += s;
    s = fmaf(a, d2, c2);         a += s;

    float4* orow = out + (size_t)warp_global * DIMV;
#pragma unroll
    for (int p = 0; p < PASSES; ++p) {
        const int idx = p * 32 + lane;
        float4 b0 = Bm[idx];
        float4 b1 = Bm[DIMV + idx];
        float4 b2 = Bm[2 * DIMV + idx];
        float4 o;
        o.x = fmaf(x[p].x, a, b0.x + b1.x + b2.x);
        o.y = fmaf(x[p].y, a, b0.y + b1.y + b2.y);
        o.z = fmaf(x[p].z, a, b0.z + b1.z + b2.z);
        o.w = fmaf(x[p].w, a, b0.w + b1.w + b2.w);
        orow[idx] = o;
    }
}

extern "C" void kernel_launch(void* const* d_in, const int* in_sizes, int n_in,
                              void* d_out, int out_size)
{
    const float4* x0 = (const float4*)d_in[0];
    const float4* W  = (const float4*)d_in[1];
    const float4* B  = (const float4*)d_in[2];
    float4* out = (float4*)d_out;

    const int batch = in_sizes[0] / 1024;
    const int threads = 256;                 // 8 warps -> 8 rows per block
    const int blocks = (batch * 32 + threads - 1) / threads;

    crossnet_kernel<<<blocks, threads>>>(x0, W, B, out, batch);
}